// round 1
// baseline (speedup 1.0000x reference)
#include <cuda_runtime.h>
#include <math.h>

// Problem dims
#define BATCH   256
#define SEQ     256
#define INPUT   128
#define HIDDEN  1024
#define ZS      1026          // Z_SIZE
#define NG      4096          // 4*HIDDEN gate count
#define KIN     1154          // original in_dim = 2 + 128 + 1024
#define KP      1168          // padded K (multiple of 16)
#define MHU     1.5f

// inp column layout (and matching repacked W layout):
//   [0,1]   = x state
//   [2,3]   = zero pad (keeps u/h blocks float4 aligned)
//   [4..131]   = u_t (128)
//   [132..1155] = h (1024)
//   [1156..1167] = zero pad
__device__ __align__(16) float g_W[NG * KP];        // ~19.1 MB repacked weights
__device__ __align__(16) float g_inp[BATCH * KP];   // persistent activation matrix
__device__ __align__(16) float g_gates[BATCH * NG]; // gate pre-activations
__device__ __align__(16) float g_c[BATCH * HIDDEN]; // cell state

// ---------------------------------------------------------------------------
// One-time (per replay) weight repack into padded layout.
// orig col k' maps: k<2 -> k'=k ; 4<=k<1156 -> k'=k-2 ; else zero
// ---------------------------------------------------------------------------
__global__ void repack_W(const float* __restrict__ WU_w) {
    int idx = blockIdx.x * blockDim.x + threadIdx.x;
    const int total = NG * KP;
    for (; idx < total; idx += gridDim.x * blockDim.x) {
        int n = idx / KP;
        int k = idx - n * KP;
        float v = 0.f;
        if (k < 2)                     v = WU_w[n * KIN + k];
        else if (k >= 4 && k < 1156)   v = WU_w[n * KIN + (k - 2)];
        g_W[idx] = v;
    }
}

// ---------------------------------------------------------------------------
// Initialize inp buffer (x from z0, u_0 from rnn_input, h from z0) and c.
// ---------------------------------------------------------------------------
__global__ void init_state(const float* __restrict__ z0,
                           const float* __restrict__ c_z0,
                           const float* __restrict__ rnn_input) {
    int b = blockIdx.x;
    int tid = threadIdx.x;
    for (int k = tid; k < KP; k += 256) {
        float v = 0.f;
        if (k < 2)                     v = z0[b * ZS + k];
        else if (k >= 4 && k < 132)    v = rnn_input[(size_t)b * SEQ * INPUT + (k - 4)];
        else if (k >= 132 && k < 1156) v = z0[b * ZS + 2 + (k - 132)];
        g_inp[b * KP + k] = v;
    }
    for (int j = tid; j < HIDDEN; j += 256)
        g_c[b * HIDDEN + j] = c_z0[b * ZS + 2 + j];
}

// ---------------------------------------------------------------------------
// SGEMM: g_gates[M=256, N=4096] = g_inp[M, KP] * g_W[N, KP]^T
// 64x64 block tile, BK=16, 256 threads, 4x4 microtile, transposed smem.
// ---------------------------------------------------------------------------
#define BM 64
#define BN 64
#define BK 16

__global__ void __launch_bounds__(256) gemm_gates() {
    __shared__ float As[BK][BM + 4];   // +4 pad keeps float4 align & eases banks
    __shared__ float Bs[BK][BN + 4];

    const int tid  = threadIdx.x;
    const int m0   = blockIdx.y * BM;
    const int n0   = blockIdx.x * BN;
    const int lrow = tid >> 2;          // 0..63 (row within tile for loads)
    const int lcol = (tid & 3) << 2;    // 0,4,8,12 (k offset, float4)
    const int tx   = tid & 15;          // n micro index
    const int ty   = tid >> 4;          // m micro index

    float acc[4][4] = {};

    const float* Aptr = g_inp + (size_t)(m0 + lrow) * KP + lcol;
    const float* Bptr = g_W   + (size_t)(n0 + lrow) * KP + lcol;

    for (int k0 = 0; k0 < KP; k0 += BK) {
        float4 av = *(const float4*)(Aptr + k0);
        float4 bv = *(const float4*)(Bptr + k0);
        As[lcol + 0][lrow] = av.x; As[lcol + 1][lrow] = av.y;
        As[lcol + 2][lrow] = av.z; As[lcol + 3][lrow] = av.w;
        Bs[lcol + 0][lrow] = bv.x; Bs[lcol + 1][lrow] = bv.y;
        Bs[lcol + 2][lrow] = bv.z; Bs[lcol + 3][lrow] = bv.w;
        __syncthreads();

        #pragma unroll
        for (int kk = 0; kk < BK; kk++) {
            float4 a = *(const float4*)&As[kk][ty << 2];
            float4 b = *(const float4*)&Bs[kk][tx << 2];
            acc[0][0] += a.x * b.x; acc[0][1] += a.x * b.y; acc[0][2] += a.x * b.z; acc[0][3] += a.x * b.w;
            acc[1][0] += a.y * b.x; acc[1][1] += a.y * b.y; acc[1][2] += a.y * b.z; acc[1][3] += a.y * b.w;
            acc[2][0] += a.z * b.x; acc[2][1] += a.z * b.y; acc[2][2] += a.z * b.z; acc[2][3] += a.z * b.w;
            acc[3][0] += a.w * b.x; acc[3][1] += a.w * b.y; acc[3][2] += a.w * b.z; acc[3][3] += a.w * b.w;
        }
        __syncthreads();
    }

    #pragma unroll
    for (int i = 0; i < 4; i++) {
        int row = m0 + (ty << 2) + i;
        float4 v = make_float4(acc[i][0], acc[i][1], acc[i][2], acc[i][3]);
        *(float4*)(g_gates + (size_t)row * NG + n0 + (tx << 2)) = v;
    }
}

// ---------------------------------------------------------------------------
// Per-step pointwise: LSTM gates, state update, alpha/hx dots, ODE mix,
// output write, stage u_{t+1}. One block per batch row.
// ---------------------------------------------------------------------------
__device__ __forceinline__ float sigm(float x) { return 1.f / (1.f + expf(-x)); }

__global__ void __launch_bounds__(256) step_pointwise(
    const float* __restrict__ rnn_input, const float* __restrict__ tau,
    const float* __restrict__ WU_b,      const float* __restrict__ alpha_w,
    const float* __restrict__ alpha_b,   const float* __restrict__ Whx_w,
    const float* __restrict__ Whx_b,     float* __restrict__ out, int t)
{
    const int b = blockIdx.x;
    const int tid = threadIdx.x;
    const int j0 = tid << 2;

    const float* gr = g_gates + (size_t)b * NG;
    float4 ig = *(const float4*)(gr + j0);
    float4 fg = *(const float4*)(gr + HIDDEN + j0);
    float4 gg = *(const float4*)(gr + 2 * HIDDEN + j0);
    float4 og = *(const float4*)(gr + 3 * HIDDEN + j0);
    float4 bi = *(const float4*)(WU_b + j0);
    float4 bf = *(const float4*)(WU_b + HIDDEN + j0);
    float4 bg = *(const float4*)(WU_b + 2 * HIDDEN + j0);
    float4 bo = *(const float4*)(WU_b + 3 * HIDDEN + j0);
    float4 c4 = *(const float4*)(g_c + (size_t)b * HIDDEN + j0);

    float iv[4] = {ig.x + bi.x, ig.y + bi.y, ig.z + bi.z, ig.w + bi.w};
    float fv[4] = {fg.x + bf.x, fg.y + bf.y, fg.z + bf.z, fg.w + bf.w};
    float gv[4] = {gg.x + bg.x, gg.y + bg.y, gg.z + bg.z, gg.w + bg.w};
    float ov[4] = {og.x + bo.x, og.y + bo.y, og.z + bo.z, og.w + bo.w};
    float cold[4] = {c4.x, c4.y, c4.z, c4.w};

    float cn[4], hn[4];
    #pragma unroll
    for (int q = 0; q < 4; q++) {
        float cne = sigm(fv[q]) * cold[q] + sigm(iv[q]) * tanhf(gv[q]);
        cn[q] = cne;
        hn[q] = sigm(ov[q]) * tanhf(cne);
    }

    *(float4*)(g_c + (size_t)b * HIDDEN + j0)   = make_float4(cn[0], cn[1], cn[2], cn[3]);
    *(float4*)(g_inp + (size_t)b * KP + 132 + j0) = make_float4(hn[0], hn[1], hn[2], hn[3]);

    float* orow = out + ((size_t)b * SEQ + t) * ZS;
    #pragma unroll
    for (int q = 0; q < 4; q++) orow[2 + j0 + q] = hn[q];

    // small dots: alpha = sigma(h @ alpha_w.T + alpha_b), hx = h @ Whx_w.T + Whx_b
    float a0 = 0.f, a1 = 0.f, w0 = 0.f, w1 = 0.f;
    #pragma unroll
    for (int q = 0; q < 4; q++) {
        float h = hn[q];
        a0 += h * alpha_w[j0 + q];
        a1 += h * alpha_w[HIDDEN + j0 + q];
        w0 += h * Whx_w[j0 + q];
        w1 += h * Whx_w[HIDDEN + j0 + q];
    }
    #pragma unroll
    for (int off = 16; off > 0; off >>= 1) {
        a0 += __shfl_down_sync(0xFFFFFFFFu, a0, off);
        a1 += __shfl_down_sync(0xFFFFFFFFu, a1, off);
        w0 += __shfl_down_sync(0xFFFFFFFFu, w0, off);
        w1 += __shfl_down_sync(0xFFFFFFFFu, w1, off);
    }
    __shared__ float red[4][8];
    if ((tid & 31) == 0) {
        int w = tid >> 5;
        red[0][w] = a0; red[1][w] = a1; red[2][w] = w0; red[3][w] = w1;
    }
    __syncthreads();
    if (tid == 0) {
        float A0 = 0.f, A1 = 0.f, W0 = 0.f, W1 = 0.f;
        #pragma unroll
        for (int w = 0; w < 8; w++) { A0 += red[0][w]; A1 += red[1][w]; W0 += red[2][w]; W1 += red[3][w]; }
        float al0 = sigm(A0 + alpha_b[0]);
        float al1 = sigm(A1 + alpha_b[1]);
        float hx0 = W0 + Whx_b[0];
        float hx1 = W1 + Whx_b[1];
        float x0 = g_inp[(size_t)b * KP + 0];
        float x1 = g_inp[(size_t)b * KP + 1];
        float tv = tau[(size_t)b * SEQ + t];
        // M = I + tau*A, A = [[mhu,-mhu],[1/mhu,0]]
        float xm0 = (1.f + tv * MHU) * x0 - (tv * MHU) * x1;
        float xm1 = (tv * (1.0f / MHU)) * x0 + x1;
        float xn0 = al0 * xm0 + (1.f - al0) * hx0;
        float xn1 = al1 * xm1 + (1.f - al1) * hx1;
        g_inp[(size_t)b * KP + 0] = xn0;
        g_inp[(size_t)b * KP + 1] = xn1;
        orow[0] = xn0;
        orow[1] = xn1;
    }
    // stage u_{t+1} for next step's GEMM
    if (t + 1 < SEQ && tid < INPUT) {
        g_inp[(size_t)b * KP + 4 + tid] =
            rnn_input[((size_t)b * SEQ + (t + 1)) * INPUT + tid];
    }
}

// ---------------------------------------------------------------------------
// Write z_f and cz_f tails of the output buffer.
// ---------------------------------------------------------------------------
__global__ void finalize(const float* __restrict__ c_z0, float* __restrict__ out) {
    int b = blockIdx.x;
    int tid = threadIdx.x;
    size_t base = (size_t)BATCH * SEQ * ZS;
    float* zf  = out + base + (size_t)b * ZS;
    float* czf = out + base + (size_t)BATCH * ZS + (size_t)b * ZS;
    for (int k = tid; k < ZS; k += 256) {
        float zv, cv;
        if (k < 2) { zv = g_inp[(size_t)b * KP + k]; cv = c_z0[b * ZS + k]; }
        else       { zv = g_inp[(size_t)b * KP + 132 + (k - 2)]; cv = g_c[(size_t)b * HIDDEN + (k - 2)]; }
        zf[k]  = zv;
        czf[k] = cv;
    }
}

// ---------------------------------------------------------------------------
extern "C" void kernel_launch(void* const* d_in, const int* in_sizes, int n_in,
                              void* d_out, int out_size) {
    const float* rnn_input = (const float*)d_in[0];
    const float* tau       = (const float*)d_in[1];
    const float* z0        = (const float*)d_in[2];
    const float* c_z0      = (const float*)d_in[3];
    const float* WU_w      = (const float*)d_in[4];
    const float* WU_b      = (const float*)d_in[5];
    const float* alpha_w   = (const float*)d_in[6];
    const float* alpha_b   = (const float*)d_in[7];
    const float* Whx_w     = (const float*)d_in[8];
    const float* Whx_b     = (const float*)d_in[9];
    float* out = (float*)d_out;

    repack_W<<<2048, 256>>>(WU_w);
    init_state<<<BATCH, 256>>>(z0, c_z0, rnn_input);

    dim3 ggrid(NG / BN, BATCH / BM);   // (64, 4)
    for (int t = 0; t < SEQ; t++) {
        gemm_gates<<<ggrid, 256>>>();
        step_pointwise<<<BATCH, 256>>>(rnn_input, tau, WU_b, alpha_w,
                                       alpha_b, Whx_w, Whx_b, out, t);
    }
    finalize<<<BATCH, 256>>>(c_z0, out);
}

// round 2
// speedup vs baseline: 1.5047x; 1.5047x over previous
#include <cuda_runtime.h>
#include <cuda_bf16.h>
#include <math.h>
#include <stdint.h>

// Problem dims
#define BATCH   256
#define SEQ     256
#define INPUT   128
#define HIDDEN  1024
#define ZS      1026
#define NG      4096          // 4*HIDDEN, interleaved: col n' = 4*j + gate
#define KIN     1154
#define KP      1168          // padded K (73 * 16)
#define NITER   73
#define MHU     1.5f

// Activation column layout: [x(2) | pad(2) | u(128) | h(1024) | pad(12)]
__device__ __align__(16) __nv_bfloat16 g_Whi[NG * KP];   // interleaved, hi part
__device__ __align__(16) __nv_bfloat16 g_Wlo[NG * KP];   // interleaved, lo part
__device__ __align__(16) float         g_bint[NG];       // interleaved bias
__device__ __align__(16) __nv_bfloat16 g_Ahi[BATCH * KP];
__device__ __align__(16) __nv_bfloat16 g_Alo[BATCH * KP];
__device__ __align__(16) float         g_c[BATCH * HIDDEN];
__device__ __align__(16) float         g_x[BATCH * 2];
__device__ __align__(16) float4        g_part[BATCH * 32]; // per-(b, n-block) dot partials

__device__ __forceinline__ float sigf(float x) {
    return __fdividef(1.f, 1.f + __expf(-x));
}
__device__ __forceinline__ float tanhfast(float x) {
    return 2.f * sigf(2.f * x) - 1.f;
}
__device__ __forceinline__ void bf16split(float v, __nv_bfloat16* hi, __nv_bfloat16* lo) {
    __nv_bfloat16 h = __float2bfloat16(v);
    *hi = h;
    *lo = __float2bfloat16(v - __bfloat162float(h));
}

// ---------------------------------------------------------------------------
// Repack weights: interleave gates, pad K, split hi/lo bf16. Bias interleave.
// ---------------------------------------------------------------------------
__global__ void repack(const float* __restrict__ WU_w, const float* __restrict__ WU_b) {
    int idx = blockIdx.x * blockDim.x + threadIdx.x;
    const int total = NG * KP;
    for (int i = idx; i < total; i += gridDim.x * blockDim.x) {
        int np = i / KP;          // interleaved col
        int k  = i - np * KP;
        int j  = np >> 2;
        int g  = np & 3;
        int n  = g * HIDDEN + j;  // original row of WU_w
        float v = 0.f;
        if (k < 2)                   v = WU_w[(size_t)n * KIN + k];
        else if (k >= 4 && k < 1156) v = WU_w[(size_t)n * KIN + (k - 2)];
        __nv_bfloat16 hi, lo;
        bf16split(v, &hi, &lo);
        g_Whi[i] = hi;
        g_Wlo[i] = lo;
    }
    if (idx < NG) {
        int j = idx >> 2, g = idx & 3;
        g_bint[idx] = WU_b[g * HIDDEN + j];
    }
}

// ---------------------------------------------------------------------------
// Init activation matrix (x, u_0, h), cell state, x state.
// ---------------------------------------------------------------------------
__global__ void init_state(const float* __restrict__ z0,
                           const float* __restrict__ c_z0,
                           const float* __restrict__ rnn_input) {
    int b = blockIdx.x, tid = threadIdx.x;
    for (int k = tid; k < KP; k += 256) {
        float v = 0.f;
        if (k < 2)                   v = z0[b * ZS + k];
        else if (k >= 4 && k < 132)  v = rnn_input[(size_t)b * SEQ * INPUT + (k - 4)];
        else if (k >= 132 && k < 1156) v = z0[b * ZS + 2 + (k - 132)];
        __nv_bfloat16 hi, lo;
        bf16split(v, &hi, &lo);
        g_Ahi[b * KP + k] = hi;
        g_Alo[b * KP + k] = lo;
    }
    if (tid < 2) g_x[b * 2 + tid] = z0[b * ZS + tid];
    for (int j = tid; j < HIDDEN; j += 256)
        g_c[b * HIDDEN + j] = c_z0[b * ZS + 2 + j];
}

// ---------------------------------------------------------------------------
// Fused GEMM (split-bf16 mma) + LSTM pointwise epilogue.
// gates[256, 4096(interleaved)] = A[256, KP] * W[4096, KP]^T
// Block tile 64x128, 8 warps (2x4), warp tile 32x32 (2 m-tiles x 4 n-tiles
// of m16n8k16). 3 mma products per tile pair: AhiWhi + AhiWlo + AloWhi.
// ---------------------------------------------------------------------------
__device__ __forceinline__ void mma16816(float* c, const uint32_t* a, const uint32_t* b) {
    asm volatile(
        "mma.sync.aligned.m16n8k16.row.col.f32.bf16.bf16.f32 "
        "{%0,%1,%2,%3}, {%4,%5,%6,%7}, {%8,%9}, {%0,%1,%2,%3};"
        : "+f"(c[0]), "+f"(c[1]), "+f"(c[2]), "+f"(c[3])
        : "r"(a[0]), "r"(a[1]), "r"(a[2]), "r"(a[3]), "r"(b[0]), "r"(b[1]));
}

// smem row stride: 24 bf16 (48 B) => conflict-free fragment loads
#define ASTRIDE 24
#define A_MAT_B (64 * ASTRIDE * 2)    // bytes per A matrix slab (3072)
#define W_MAT_B (128 * ASTRIDE * 2)   // bytes per W matrix slab (6144)

__global__ void __launch_bounds__(256) gemm_fused(
    const float* __restrict__ alpha_w, const float* __restrict__ Whx_w,
    float* __restrict__ out, int t)
{
    __shared__ __align__(16) unsigned char smA[2 * A_MAT_B];   // hi, lo
    __shared__ __align__(16) unsigned char smW[2 * W_MAT_B];   // hi, lo
    __shared__ __align__(16) float4 part[64][4];               // [row][warp_n]

    const int tid = threadIdx.x;
    const int n0 = blockIdx.x * 128;   // gate-col base (interleaved)
    const int m0 = blockIdx.y * 64;    // batch base
    const int lane = tid & 31, wid = tid >> 5;
    const int warp_m = wid >> 2, warp_n = wid & 3;
    const int r = lane >> 2, q = lane & 3;

    // --- staging assignments ---
    const int arow = (tid & 127) >> 1;       // 0..63
    const int acol8 = tid & 1;
    const __nv_bfloat16* Abase =
        (tid < 128 ? g_Ahi : g_Alo) + (size_t)(m0 + arow) * KP + acol8 * 8;
    const int wrow = tid >> 1;               // 0..127
    const int wcol8 = tid & 1;
    const __nv_bfloat16* Whb = g_Whi + (size_t)(n0 + wrow) * KP + wcol8 * 8;
    const __nv_bfloat16* Wlb = g_Wlo + (size_t)(n0 + wrow) * KP + wcol8 * 8;

    uint4* smA_dst = (uint4*)(smA + (tid < 128 ? 0 : A_MAT_B) + arow * 48 + acol8 * 16);
    uint4* smWh_dst = (uint4*)(smW + wrow * 48 + wcol8 * 16);
    uint4* smWl_dst = (uint4*)(smW + W_MAT_B + wrow * 48 + wcol8 * 16);

    const uint32_t* As32 = (const uint32_t*)smA;   // [mat][64][12]
    const uint32_t* Ws32 = (const uint32_t*)smW;   // [mat][128][12]

    float acc[2][4][4] = {};

    // prologue: tile 0
    uint4 sa = *(const uint4*)(Abase);
    uint4 swh = *(const uint4*)(Whb);
    uint4 swl = *(const uint4*)(Wlb);
    *smA_dst = sa; *smWh_dst = swh; *smWl_dst = swl;
    __syncthreads();

    for (int it = 0; it < NITER; it++) {
        uint4 na, nwh, nwl;
        const bool more = (it + 1 < NITER);
        if (more) {
            int kn = (it + 1) * 16;
            na  = *(const uint4*)(Abase + kn);
            nwh = *(const uint4*)(Whb + kn);
            nwl = *(const uint4*)(Wlb + kn);
        }

        // fragment loads
        uint32_t ah[2][4], al[2][4], bh[4][2], bl[4][2];
        #pragma unroll
        for (int i = 0; i < 2; i++) {
            int row = warp_m * 32 + i * 16 + r;
            ah[i][0] = As32[row * 12 + q];
            ah[i][1] = As32[(row + 8) * 12 + q];
            ah[i][2] = As32[row * 12 + q + 4];
            ah[i][3] = As32[(row + 8) * 12 + q + 4];
            const uint32_t* Al = As32 + (A_MAT_B / 4);
            al[i][0] = Al[row * 12 + q];
            al[i][1] = Al[(row + 8) * 12 + q];
            al[i][2] = Al[row * 12 + q + 4];
            al[i][3] = Al[(row + 8) * 12 + q + 4];
        }
        #pragma unroll
        for (int j = 0; j < 4; j++) {
            int nrow = warp_n * 32 + j * 8 + r;
            bh[j][0] = Ws32[nrow * 12 + q];
            bh[j][1] = Ws32[nrow * 12 + q + 4];
            const uint32_t* Wl = Ws32 + (W_MAT_B / 4);
            bl[j][0] = Wl[nrow * 12 + q];
            bl[j][1] = Wl[nrow * 12 + q + 4];
        }
        #pragma unroll
        for (int i = 0; i < 2; i++)
            #pragma unroll
            for (int j = 0; j < 4; j++) {
                mma16816(acc[i][j], ah[i], bh[j]);
                mma16816(acc[i][j], ah[i], bl[j]);
                mma16816(acc[i][j], al[i], bh[j]);
            }

        if (more) {
            __syncthreads();
            *smA_dst = na; *smWh_dst = nwh; *smWl_dst = nwl;
            __syncthreads();
        }
    }

    // ----------------- fused LSTM epilogue -----------------
    const int parity = q & 1;   // 0: lane holds i,f ; 1: lane holds g,o
    const int jj = q >> 1;

    #pragma unroll
    for (int i = 0; i < 2; i++) {
        float d0 = 0.f, d1 = 0.f, d2 = 0.f, d3 = 0.f;
        const int row_blk = warp_m * 32 + i * 16 + r + parity * 8;
        const int b = m0 + row_blk;
        #pragma unroll
        for (int j = 0; j < 4; j++) {
            float c0 = acc[i][j][0], c1 = acc[i][j][1], c2 = acc[i][j][2], c3 = acc[i][j][3];
            float p0 = __shfl_xor_sync(0xffffffffu, c0, 1);
            float p1 = __shfl_xor_sync(0xffffffffu, c1, 1);
            float p2 = __shfl_xor_sync(0xffffffffu, c2, 1);
            float p3 = __shfl_xor_sync(0xffffffffu, c3, 1);
            float gi, gf, gg, go;
            if (!parity) { gi = c0; gf = c1; gg = p0; go = p1; }   // row r
            else         { gi = p2; gf = p3; gg = c2; go = c3; }   // row r+8
            const int jg = (n0 >> 2) + warp_n * 8 + j * 2 + jj;    // hidden idx
            float4 bv = *(const float4*)(g_bint + 4 * jg);
            gi += bv.x; gf += bv.y; gg += bv.z; go += bv.w;
            float co = g_c[b * HIDDEN + jg];
            float cn = sigf(gf) * co + sigf(gi) * tanhfast(gg);
            float h  = sigf(go) * tanhfast(cn);
            g_c[b * HIDDEN + jg] = cn;
            out[((size_t)b * SEQ + t) * ZS + 2 + jg] = h;
            __nv_bfloat16 hh, hl;
            bf16split(h, &hh, &hl);
            g_Ahi[b * KP + 132 + jg] = hh;
            g_Alo[b * KP + 132 + jg] = hl;
            d0 += h * alpha_w[jg];
            d1 += h * alpha_w[HIDDEN + jg];
            d2 += h * Whx_w[jg];
            d3 += h * Whx_w[HIDDEN + jg];
        }
        d0 += __shfl_xor_sync(0xffffffffu, d0, 2);
        d1 += __shfl_xor_sync(0xffffffffu, d1, 2);
        d2 += __shfl_xor_sync(0xffffffffu, d2, 2);
        d3 += __shfl_xor_sync(0xffffffffu, d3, 2);
        if (q < 2) part[row_blk][warp_n] = make_float4(d0, d1, d2, d3);
    }
    __syncthreads();
    if (tid < 64) {
        float4 a = part[tid][0], bb = part[tid][1], c = part[tid][2], d = part[tid][3];
        float4 s = make_float4(a.x + bb.x + c.x + d.x, a.y + bb.y + c.y + d.y,
                               a.z + bb.z + c.z + d.z, a.w + bb.w + c.w + d.w);
        g_part[(m0 + tid) * 32 + blockIdx.x] = s;
    }
}

// ---------------------------------------------------------------------------
// Per-step finish: reduce dot partials, ODE x-update, stage u_{t+1}.
// One block per batch row, 128 threads.
// ---------------------------------------------------------------------------
__global__ void __launch_bounds__(128) finish_step(
    const float* __restrict__ rnn_input, const float* __restrict__ tau,
    const float* __restrict__ alpha_b,   const float* __restrict__ Whx_b,
    float* __restrict__ out, int t)
{
    const int b = blockIdx.x, tid = threadIdx.x;
    if (tid < 32) {
        float4 p = g_part[b * 32 + tid];
        #pragma unroll
        for (int off = 16; off > 0; off >>= 1) {
            p.x += __shfl_xor_sync(0xffffffffu, p.x, off);
            p.y += __shfl_xor_sync(0xffffffffu, p.y, off);
            p.z += __shfl_xor_sync(0xffffffffu, p.z, off);
            p.w += __shfl_xor_sync(0xffffffffu, p.w, off);
        }
        if (tid == 0) {
            float al0 = sigf(p.x + alpha_b[0]);
            float al1 = sigf(p.y + alpha_b[1]);
            float hx0 = p.z + Whx_b[0];
            float hx1 = p.w + Whx_b[1];
            float x0 = g_x[b * 2], x1 = g_x[b * 2 + 1];
            float tv = tau[(size_t)b * SEQ + t];
            float xm0 = (1.f + tv * MHU) * x0 - (tv * MHU) * x1;
            float xm1 = tv * (1.f / MHU) * x0 + x1;
            float xn0 = al0 * xm0 + (1.f - al0) * hx0;
            float xn1 = al1 * xm1 + (1.f - al1) * hx1;
            g_x[b * 2] = xn0; g_x[b * 2 + 1] = xn1;
            float* orow = out + ((size_t)b * SEQ + t) * ZS;
            orow[0] = xn0; orow[1] = xn1;
            __nv_bfloat16 hi, lo;
            bf16split(xn0, &hi, &lo);
            g_Ahi[b * KP + 0] = hi; g_Alo[b * KP + 0] = lo;
            bf16split(xn1, &hi, &lo);
            g_Ahi[b * KP + 1] = hi; g_Alo[b * KP + 1] = lo;
        }
    }
    if (t + 1 < SEQ) {
        float u = rnn_input[((size_t)b * SEQ + (t + 1)) * INPUT + tid];
        __nv_bfloat16 hi, lo;
        bf16split(u, &hi, &lo);
        g_Ahi[b * KP + 4 + tid] = hi;
        g_Alo[b * KP + 4 + tid] = lo;
    }
}

// ---------------------------------------------------------------------------
// Tail: z_f = out[:, SEQ-1, :]; cz_f = [c_z0[:, :2], c_final]
// ---------------------------------------------------------------------------
__global__ void finalize(const float* __restrict__ c_z0, float* __restrict__ out) {
    int b = blockIdx.x, tid = threadIdx.x;
    size_t base = (size_t)BATCH * SEQ * ZS;
    float* zf  = out + base + (size_t)b * ZS;
    float* czf = out + base + (size_t)BATCH * ZS + (size_t)b * ZS;
    const float* last = out + ((size_t)b * SEQ + (SEQ - 1)) * ZS;
    for (int k = tid; k < ZS; k += 256) {
        zf[k] = last[k];
        czf[k] = (k < 2) ? c_z0[b * ZS + k] : g_c[(size_t)b * HIDDEN + (k - 2)];
    }
}

// ---------------------------------------------------------------------------
extern "C" void kernel_launch(void* const* d_in, const int* in_sizes, int n_in,
                              void* d_out, int out_size) {
    const float* rnn_input = (const float*)d_in[0];
    const float* tau       = (const float*)d_in[1];
    const float* z0        = (const float*)d_in[2];
    const float* c_z0      = (const float*)d_in[3];
    const float* WU_w      = (const float*)d_in[4];
    const float* WU_b      = (const float*)d_in[5];
    const float* alpha_w   = (const float*)d_in[6];
    const float* alpha_b   = (const float*)d_in[7];
    const float* Whx_w     = (const float*)d_in[8];
    const float* Whx_b     = (const float*)d_in[9];
    float* out = (float*)d_out;

    repack<<<4096, 256>>>(WU_w, WU_b);
    init_state<<<BATCH, 256>>>(z0, c_z0, rnn_input);

    dim3 ggrid(32, 4);   // N/128, M/64
    for (int t = 0; t < SEQ; t++) {
        gemm_fused<<<ggrid, 256>>>(alpha_w, Whx_w, out, t);
        finish_step<<<BATCH, 128>>>(rnn_input, tau, alpha_b, Whx_b, out, t);
    }
    finalize<<<BATCH, 256>>>(c_z0, out);
}